// round 1
// baseline (speedup 1.0000x reference)
#include <cuda_runtime.h>
#include <math.h>

#define BB 32
#define TT 512
#define DD 512
#define EE 8
#define HH 2048

// Scratch (no cudaMalloc allowed): h = relu(x@W1+b1), [B, T, H] fp32 = 128 MB
__device__ float g_h[(size_t)BB * TT * HH];
__device__ int   g_expert[BB];

// ---------------------------------------------------------------------------
// Router: pooled = mean_t x[b,t,:]; logits = pooled@Wp + bp; softmax; argmax.
// One CTA per batch, 256 threads.
// ---------------------------------------------------------------------------
__global__ void router_kernel(const float* __restrict__ x,
                              const float* __restrict__ Wp,
                              const float* __restrict__ bp,
                              float* __restrict__ out_tail) // d_out + B*T*D
{
    int b   = blockIdx.x;
    int tid = threadIdx.x;

    __shared__ float pooled[DD];
    __shared__ float logits[EE];

    // pooled[d] = mean over t (coalesced across threads at each t)
    for (int d = tid; d < DD; d += 256) {
        const float* xp = x + (size_t)b * TT * DD + d;
        float s = 0.f;
        #pragma unroll 8
        for (int t = 0; t < TT; ++t) s += xp[(size_t)t * DD];
        pooled[d] = s * (1.0f / TT);
    }
    __syncthreads();

    // 8 warps -> 8 experts
    int warp = tid >> 5, lane = tid & 31;
    if (warp < EE) {
        float s = 0.f;
        for (int d = lane; d < DD; d += 32)
            s += pooled[d] * Wp[(size_t)d * EE + warp];
        #pragma unroll
        for (int o = 16; o > 0; o >>= 1) s += __shfl_xor_sync(0xffffffffu, s, o);
        if (lane == 0) logits[warp] = s + bp[warp];
    }
    __syncthreads();

    if (tid == 0) {
        float m = logits[0]; int arg = 0;
        #pragma unroll
        for (int e = 1; e < EE; ++e)
            if (logits[e] > m) { m = logits[e]; arg = e; }
        float p[EE]; float sum = 0.f;
        #pragma unroll
        for (int e = 0; e < EE; ++e) { p[e] = __expf(logits[e] - m); sum += p[e]; }
        float inv = 1.0f / sum;
        #pragma unroll
        for (int e = 0; e < EE; ++e)
            out_tail[b * EE + e] = p[e] * inv;          // probs [B,E]
        out_tail[BB * EE + b] = (float)arg;             // expert_chosen [B,1] as float
        g_expert[b] = arg;
    }
}

// ---------------------------------------------------------------------------
// Batched SGEMM: C[b] = act(A[b](MxK) @ W[expert(b)](KxN) + bias[expert(b)])
// 128x128 tile, BK=8, 8x8 per thread, 256 threads, float4 loads.
// A==nullptr -> use g_h as A; C==nullptr -> use g_h as C.
// ---------------------------------------------------------------------------
template <bool RELU, bool A_IS_SCRATCH, bool C_IS_SCRATCH>
__global__ __launch_bounds__(256)
void ffn_gemm(const float* __restrict__ A,
              const float* __restrict__ W,     // [E, K, N]
              const float* __restrict__ bias,  // [E, N]
              float* __restrict__ C,
              int M, int N, int K)
{
    constexpr int BM = 128, BN = 128, BK = 8, TM = 8, TN = 8;

    __shared__ float As[BK][BM];
    __shared__ float Bs[BK][BN];

    const int b = blockIdx.z;
    const int e = g_expert[b];

    const float* Ab = (A_IS_SCRATCH ? g_h : A) + (size_t)b * M * K;
    const float* Wb = W + (size_t)e * K * N;
    const float* biasb = bias + (size_t)e * N;
    float* Cb = (C_IS_SCRATCH ? g_h : C) + (size_t)b * M * N;

    const int tid = threadIdx.x;
    const int blockRow = blockIdx.y * BM;
    const int blockCol = blockIdx.x * BN;

    // load mapping
    const int aRow = tid >> 1;            // 0..127
    const int aCol = (tid & 1) * 4;       // 0 or 4
    const int bRow = tid >> 5;            // 0..7
    const int bCol = (tid & 31) * 4;      // 0..124

    // compute mapping
    const int ty = tid >> 4;              // 0..15
    const int tx = tid & 15;              // 0..15

    float acc[TM][TN];
    #pragma unroll
    for (int i = 0; i < TM; ++i)
        #pragma unroll
        for (int j = 0; j < TN; ++j) acc[i][j] = 0.f;

    for (int k0 = 0; k0 < K; k0 += BK) {
        float4 a4 = *reinterpret_cast<const float4*>(
            Ab + (size_t)(blockRow + aRow) * K + k0 + aCol);
        As[aCol + 0][aRow] = a4.x;
        As[aCol + 1][aRow] = a4.y;
        As[aCol + 2][aRow] = a4.z;
        As[aCol + 3][aRow] = a4.w;

        *reinterpret_cast<float4*>(&Bs[bRow][bCol]) =
            *reinterpret_cast<const float4*>(
                Wb + (size_t)(k0 + bRow) * N + blockCol + bCol);
        __syncthreads();

        #pragma unroll
        for (int k = 0; k < BK; ++k) {
            float ra[TM], rb[TN];
            #pragma unroll
            for (int i = 0; i < TM; ++i) ra[i] = As[k][ty * TM + i];
            #pragma unroll
            for (int j = 0; j < TN; ++j) rb[j] = Bs[k][tx * TN + j];
            #pragma unroll
            for (int i = 0; i < TM; ++i)
                #pragma unroll
                for (int j = 0; j < TN; ++j)
                    acc[i][j] = fmaf(ra[i], rb[j], acc[i][j]);
        }
        __syncthreads();
    }

    // epilogue: bias (+relu), vectorized stores
    #pragma unroll
    for (int i = 0; i < TM; ++i) {
        const int row = blockRow + ty * TM + i;
        #pragma unroll
        for (int j = 0; j < TN; j += 4) {
            const int col = blockCol + tx * TN + j;
            float4 v;
            v.x = acc[i][j + 0] + biasb[col + 0];
            v.y = acc[i][j + 1] + biasb[col + 1];
            v.z = acc[i][j + 2] + biasb[col + 2];
            v.w = acc[i][j + 3] + biasb[col + 3];
            if (RELU) {
                v.x = fmaxf(v.x, 0.f); v.y = fmaxf(v.y, 0.f);
                v.z = fmaxf(v.z, 0.f); v.w = fmaxf(v.w, 0.f);
            }
            *reinterpret_cast<float4*>(Cb + (size_t)row * N + col) = v;
        }
    }
}

// ---------------------------------------------------------------------------
// Launch. Inputs (metadata order): x, Wp, bp, W1, b1, W2, b2.
// Output layout: [final (B*T*D) | probs (B*E) | expert_chosen (B) as float].
// ---------------------------------------------------------------------------
extern "C" void kernel_launch(void* const* d_in, const int* in_sizes, int n_in,
                              void* d_out, int out_size)
{
    const float* x  = (const float*)d_in[0];
    const float* Wp = (const float*)d_in[1];
    const float* bp = (const float*)d_in[2];
    const float* W1 = (const float*)d_in[3];
    const float* b1 = (const float*)d_in[4];
    const float* W2 = (const float*)d_in[5];
    const float* b2 = (const float*)d_in[6];
    float* out = (float*)d_out;

    // 1) Router (writes probs + chosen to the output tail and g_expert)
    router_kernel<<<BB, 256>>>(x, Wp, bp, out + (size_t)BB * TT * DD);

    // 2) h = relu(x @ W1[e] + b1[e])   M=T, N=H, K=D
    {
        dim3 grid(HH / 128, TT / 128, BB);
        ffn_gemm<true, false, true><<<grid, 256>>>(x, W1, b1, nullptr, TT, HH, DD);
    }

    // 3) out = h @ W2[e] + b2[e]       M=T, N=D, K=H
    {
        dim3 grid(DD / 128, TT / 128, BB);
        ffn_gemm<false, true, false><<<grid, 256>>>(nullptr, W2, b2, out, TT, DD, HH);
    }
}

// round 3
// speedup vs baseline: 2.4707x; 2.4707x over previous
#include <cuda_runtime.h>
#include <cstdint>

#define BB 32
#define TT 512
#define DD 512
#define EE 8
#define HH 2048

// ---------------- device scratch (no cudaMalloc allowed) -------------------
__device__ uint32_t g_h[(size_t)BB * TT * HH];     // h (relu'd, tf32 bits)  128 MB
__device__ uint32_t g_x[(size_t)BB * TT * DD];     // x as tf32 bits          32 MB
__device__ uint32_t g_W1t[(size_t)EE * HH * DD];   // W1^T tf32 [E][H][D]     64 MB
__device__ uint32_t g_W2t[(size_t)EE * DD * HH];   // W2^T tf32 [E][D][H]     64 MB
__device__ float    g_part[BB * 8 * DD];
__device__ int      g_expert[BB];

// ---------------- helpers ---------------------------------------------------
__device__ __forceinline__ uint32_t smem_u32(const void* p) {
    uint32_t a;
    asm("{ .reg .u64 t; cvta.to.shared.u64 t, %1; cvt.u32.u64 %0, t; }" : "=r"(a) : "l"(p));
    return a;
}
__device__ __forceinline__ uint32_t f2tf(float x) {   // round-to-nearest tf32
    uint32_t r; asm("cvt.rn.tf32.f32 %0, %1;" : "=r"(r) : "f"(x)); return r;
}
#define SWZ(o) ((o) ^ ((((uint32_t)(o)) >> 3) & 0x70u))

__device__ __forceinline__ void cp_async16(uint32_t dst, const void* src) {
    asm volatile("cp.async.cg.shared.global [%0], [%1], 16;" :: "r"(dst), "l"(src));
}
__device__ __forceinline__ void cp_commit() {
    asm volatile("cp.async.commit_group;" ::: "memory");
}
__device__ __forceinline__ void cp_wait1() {
    asm volatile("cp.async.wait_group 1;" ::: "memory");
}
__device__ __forceinline__ void ldsm4(uint32_t* r, uint32_t addr) {
    asm volatile("ldmatrix.sync.aligned.m8n8.x4.shared.b16 {%0,%1,%2,%3}, [%4];"
                 : "=r"(r[0]), "=r"(r[1]), "=r"(r[2]), "=r"(r[3]) : "r"(addr));
}
__device__ __forceinline__ void mma1688(float* d, const uint32_t* a, uint32_t b0, uint32_t b1) {
    asm volatile("mma.sync.aligned.m16n8k8.row.col.f32.tf32.tf32.f32 "
                 "{%0,%1,%2,%3}, {%4,%5,%6,%7}, {%8,%9}, {%0,%1,%2,%3};"
                 : "+f"(d[0]), "+f"(d[1]), "+f"(d[2]), "+f"(d[3])
                 : "r"(a[0]), "r"(a[1]), "r"(a[2]), "r"(a[3]), "r"(b0), "r"(b1));
}

// ---------------- router (fused x -> tf32 convert + pooling) ----------------
__global__ void convert_pool(const float* __restrict__ x, uint32_t* __restrict__ xt,
                             float* __restrict__ part) {
    int b = blockIdx.x, s = blockIdx.y, tid = threadIdx.x;
    size_t base = ((size_t)b * TT + s * 64) * DD;
    float s0 = 0.f, s1 = 0.f;
    #pragma unroll 4
    for (int t = 0; t < 64; ++t) {
        float v0 = x[base + (size_t)t * DD + tid];
        float v1 = x[base + (size_t)t * DD + tid + 256];
        s0 += v0; s1 += v1;
        xt[base + (size_t)t * DD + tid]       = f2tf(v0);
        xt[base + (size_t)t * DD + tid + 256] = f2tf(v1);
    }
    part[((size_t)b * 8 + s) * DD + tid]       = s0;
    part[((size_t)b * 8 + s) * DD + tid + 256] = s1;
}

__global__ void router_final(const float* __restrict__ part,
                             const float* __restrict__ Wp,
                             const float* __restrict__ bp,
                             float* __restrict__ out_tail) {
    int b = blockIdx.x, tid = threadIdx.x;
    __shared__ float pooled[DD];
    __shared__ float logits[EE];

    for (int d = tid; d < DD; d += 256) {
        float s = 0.f;
        #pragma unroll
        for (int p = 0; p < 8; ++p) s += part[((size_t)b * 8 + p) * DD + d];
        pooled[d] = s * (1.0f / TT);
    }
    __syncthreads();

    int warp = tid >> 5, lane = tid & 31;
    if (warp < EE) {
        float s = 0.f;
        for (int d = lane; d < DD; d += 32) s += pooled[d] * Wp[(size_t)d * EE + warp];
        #pragma unroll
        for (int o = 16; o > 0; o >>= 1) s += __shfl_xor_sync(0xffffffffu, s, o);
        if (lane == 0) logits[warp] = s + bp[warp];
    }
    __syncthreads();

    if (tid == 0) {
        float m = logits[0]; int arg = 0;
        #pragma unroll
        for (int e = 1; e < EE; ++e) if (logits[e] > m) { m = logits[e]; arg = e; }
        float p[EE], sum = 0.f;
        #pragma unroll
        for (int e = 0; e < EE; ++e) { p[e] = __expf(logits[e] - m); sum += p[e]; }
        float inv = 1.0f / sum;
        #pragma unroll
        for (int e = 0; e < EE; ++e) out_tail[b * EE + e] = p[e] * inv;
        out_tail[BB * EE + b] = (float)arg;
        g_expert[b] = arg;
    }
}

// ---------------- weight transpose + tf32 rounding ---------------------------
// src: [E][R][C] fp32  ->  dst: [E][C][R] tf32 bits
__global__ void transpose_tf32(const float* __restrict__ src, uint32_t* __restrict__ dst,
                               int R, int C) {
    __shared__ uint32_t tile[32][33];
    int e = blockIdx.z;
    src += (size_t)e * R * C;
    dst += (size_t)e * R * C;
    int c0 = blockIdx.x * 32, r0 = blockIdx.y * 32;
    int tx = threadIdx.x, ty = threadIdx.y;
    #pragma unroll
    for (int j = 0; j < 32; j += 8)
        tile[ty + j][tx] = f2tf(src[(size_t)(r0 + ty + j) * C + c0 + tx]);
    __syncthreads();
    #pragma unroll
    for (int j = 0; j < 32; j += 8)
        dst[(size_t)(c0 + ty + j) * R + r0 + tx] = tile[tx][ty + j];
}

// ---------------- tf32 mma.sync GEMM -----------------------------------------
// C[b](TT x ND) = act(A[b](TT x KD) @ Bt[e]^T + bias[e]);  Bt: [E][ND][KD]
// CTA tile 128x128, BK=32, 3-stage cp.async pipeline, 8 warps (warp tile 64x32).
template <int KD, int ND, bool RELU, bool OUT_TF32>
__global__ __launch_bounds__(256, 1)
void moe_gemm(const uint32_t* __restrict__ A, const uint32_t* __restrict__ Bt,
              const float* __restrict__ bias, uint32_t* __restrict__ C) {
    extern __shared__ uint8_t smraw[];
    const int tid = threadIdx.x, wid = tid >> 5, lane = tid & 31;
    const int b = blockIdx.z;
    const int e = g_expert[b];
    const int row0 = blockIdx.y * 128;
    const int col0 = blockIdx.x * 128;

    const uint32_t* Ab = A + (size_t)b * TT * KD;
    const uint32_t* Bb = Bt + (size_t)e * ND * KD;
    const float* biasb = bias + (size_t)e * ND;
    uint32_t* Cb = C + (size_t)b * TT * ND;

    const uint32_t smBase = smem_u32(smraw);
    const int lr = tid >> 3;   // loader row (0..31)
    const int lc = tid & 7;    // loader 16B chunk (0..7)

    constexpr int NC = KD / 32;

    auto issue = [&](int c) {
        if (c < NC) {
            uint32_t sA = smBase + (uint32_t)(c % 3) * 32768u;
            uint32_t sB = sA + 16384u;
            int k0 = c * 32;
            #pragma unroll
            for (int i = 0; i < 4; ++i) {
                int r = lr + 32 * i;
                cp_async16(sA + SWZ((uint32_t)(r * 128 + lc * 16)),
                           Ab + (size_t)(row0 + r) * KD + k0 + lc * 4);
            }
            #pragma unroll
            for (int i = 0; i < 4; ++i) {
                int r = lr + 32 * i;
                cp_async16(sB + SWZ((uint32_t)(r * 128 + lc * 16)),
                           Bb + (size_t)(col0 + r) * KD + k0 + lc * 4);
            }
        }
        cp_commit();
    };

    issue(0);
    issue(1);

    const int wm = wid >> 2;   // 0..1
    const int wn = wid & 3;    // 0..3
    const int mi = lane >> 3;  // ldmatrix sub-matrix index

    float acc[4][4][4];
    #pragma unroll
    for (int mt = 0; mt < 4; ++mt)
        #pragma unroll
        for (int nt = 0; nt < 4; ++nt)
            #pragma unroll
            for (int k = 0; k < 4; ++k) acc[mt][nt][k] = 0.f;

    #pragma unroll 1
    for (int c = 0; c < NC; ++c) {
        cp_wait1();
        __syncthreads();
        issue(c + 2);

        uint32_t sA = smBase + (uint32_t)(c % 3) * 32768u;
        uint32_t sB = sA + 16384u;

        #pragma unroll
        for (int ks = 0; ks < 4; ++ks) {
            uint32_t af[4][4];
            #pragma unroll
            for (int mt = 0; mt < 4; ++mt) {
                int row = wm * 64 + mt * 16 + (mi & 1) * 8 + (lane & 7);
                ldsm4(af[mt], sA + SWZ((uint32_t)(row * 128 + ks * 32 + (mi >> 1) * 16)));
            }
            uint32_t bf[2][4];
            #pragma unroll
            for (int np = 0; np < 2; ++np) {
                int row = wn * 32 + np * 16 + (mi >> 1) * 8 + (lane & 7);
                ldsm4(bf[np], sB + SWZ((uint32_t)(row * 128 + ks * 32 + (mi & 1) * 16)));
            }
            #pragma unroll
            for (int mt = 0; mt < 4; ++mt)
                #pragma unroll
                for (int nt = 0; nt < 4; ++nt) {
                    const uint32_t* bp = &bf[nt >> 1][(nt & 1) * 2];
                    mma1688(acc[mt][nt], af[mt], bp[0], bp[1]);
                }
        }
    }

    // ---------------- epilogue: bias (+relu), float2 stores ----------------
    #pragma unroll
    for (int mt = 0; mt < 4; ++mt) {
        #pragma unroll
        for (int nt = 0; nt < 4; ++nt) {
            int col = col0 + wn * 32 + nt * 8 + (lane & 3) * 2;
            float bv0 = __ldg(biasb + col);
            float bv1 = __ldg(biasb + col + 1);
            #pragma unroll
            for (int h = 0; h < 2; ++h) {
                int row = row0 + wm * 64 + mt * 16 + (lane >> 2) + h * 8;
                float v0 = acc[mt][nt][h * 2 + 0] + bv0;
                float v1 = acc[mt][nt][h * 2 + 1] + bv1;
                if (RELU) { v0 = fmaxf(v0, 0.f); v1 = fmaxf(v1, 0.f); }
                uint2 u;
                u.x = OUT_TF32 ? f2tf(v0) : __float_as_uint(v0);
                u.y = OUT_TF32 ? f2tf(v1) : __float_as_uint(v1);
                *reinterpret_cast<uint2*>(Cb + (size_t)row * ND + col) = u;
            }
        }
    }
}

// ---------------- launch -----------------------------------------------------
extern "C" void kernel_launch(void* const* d_in, const int* in_sizes, int n_in,
                              void* d_out, int out_size) {
    const float* x  = (const float*)d_in[0];
    const float* Wp = (const float*)d_in[1];
    const float* bp = (const float*)d_in[2];
    const float* W1 = (const float*)d_in[3];
    const float* b1 = (const float*)d_in[4];
    const float* W2 = (const float*)d_in[5];
    const float* b2 = (const float*)d_in[6];
    float* out = (float*)d_out;

    void *pW1t, *pW2t, *pH, *pX, *pPart;
    cudaGetSymbolAddress(&pW1t, g_W1t);
    cudaGetSymbolAddress(&pW2t, g_W2t);
    cudaGetSymbolAddress(&pH, g_h);
    cudaGetSymbolAddress(&pX, g_x);
    cudaGetSymbolAddress(&pPart, g_part);

    const int SMEM = 98304;
    cudaFuncSetAttribute(moe_gemm<DD, HH, true, true>,
                         cudaFuncAttributeMaxDynamicSharedMemorySize, SMEM);
    cudaFuncSetAttribute(moe_gemm<HH, DD, false, false>,
                         cudaFuncAttributeMaxDynamicSharedMemorySize, SMEM);

    // router + x -> tf32
    convert_pool<<<dim3(BB, 8), 256>>>(x, (uint32_t*)pX, (float*)pPart);
    router_final<<<BB, 256>>>((const float*)pPart, Wp, bp, out + (size_t)BB * TT * DD);

    // weight transposes (fp32 -> tf32 bits, K-major [E][N][K])
    transpose_tf32<<<dim3(HH / 32, DD / 32, EE), dim3(32, 8)>>>(W1, (uint32_t*)pW1t, DD, HH);
    transpose_tf32<<<dim3(DD / 32, HH / 32, EE), dim3(32, 8)>>>(W2, (uint32_t*)pW2t, HH, DD);

    // h = relu(x @ W1[e] + b1[e])
    moe_gemm<DD, HH, true, true>
        <<<dim3(HH / 128, TT / 128, BB), 256, SMEM>>>(
            (const uint32_t*)pX, (const uint32_t*)pW1t, b1, (uint32_t*)pH);

    // out = h @ W2[e] + b2[e]
    moe_gemm<HH, DD, false, false>
        <<<dim3(DD / 128, TT / 128, BB), 256, SMEM>>>(
            (const uint32_t*)pH, (const uint32_t*)pW2t, b2, (uint32_t*)out);
}

// round 4
// speedup vs baseline: 4.6582x; 1.8854x over previous
#include <cuda_runtime.h>
#include <cstdint>

#define BB 32
#define TT 512
#define DD 512
#define EE 8
#define HH 2048

// ---------------- device scratch (no cudaMalloc allowed) -------------------
__device__ uint32_t g_h[(size_t)BB * TT * HH];     // h (relu'd, tf32 bits)  128 MB
__device__ uint32_t g_x[(size_t)BB * TT * DD];     // x as tf32 bits          32 MB
__device__ uint32_t g_W1t[(size_t)EE * HH * DD];   // W1^T tf32 [E][H][D]     64 MB
__device__ uint32_t g_W2t[(size_t)EE * DD * HH];   // W2^T tf32 [E][D][H]     64 MB
__device__ float    g_part[BB * 8 * DD];
__device__ int      g_expert[BB];

// ---------------- helpers ---------------------------------------------------
__device__ __forceinline__ uint32_t smem_u32(const void* p) {
    uint32_t a;
    asm("{ .reg .u64 t; cvta.to.shared.u64 t, %1; cvt.u32.u64 %0, t; }" : "=r"(a) : "l"(p));
    return a;
}
__device__ __forceinline__ uint32_t f2tf(float x) {   // round-to-nearest tf32
    uint32_t r; asm("cvt.rn.tf32.f32 %0, %1;" : "=r"(r) : "f"(x)); return r;
}
#define SWZ(o) ((o) ^ ((((uint32_t)(o)) >> 3) & 0x70u))

__device__ __forceinline__ void cp_async16(uint32_t dst, const void* src) {
    asm volatile("cp.async.cg.shared.global [%0], [%1], 16;" :: "r"(dst), "l"(src));
}
__device__ __forceinline__ void cp_commit() {
    asm volatile("cp.async.commit_group;" ::: "memory");
}
__device__ __forceinline__ void cp_wait1() {
    asm volatile("cp.async.wait_group 1;" ::: "memory");
}
__device__ __forceinline__ void ldsm4(uint32_t* r, uint32_t addr) {
    asm volatile("ldmatrix.sync.aligned.m8n8.x4.shared.b16 {%0,%1,%2,%3}, [%4];"
                 : "=r"(r[0]), "=r"(r[1]), "=r"(r[2]), "=r"(r[3]) : "r"(addr));
}
__device__ __forceinline__ void mma1688(float* d, const uint32_t* a, uint32_t b0, uint32_t b1) {
    asm volatile("mma.sync.aligned.m16n8k8.row.col.f32.tf32.tf32.f32 "
                 "{%0,%1,%2,%3}, {%4,%5,%6,%7}, {%8,%9}, {%0,%1,%2,%3};"
                 : "+f"(d[0]), "+f"(d[1]), "+f"(d[2]), "+f"(d[3])
                 : "r"(a[0]), "r"(a[1]), "r"(a[2]), "r"(a[3]), "r"(b0), "r"(b1));
}

// ---------------- router (fused x -> tf32 convert + pooling) ----------------
__global__ void convert_pool(const float* __restrict__ x, uint32_t* __restrict__ xt,
                             float* __restrict__ part) {
    int b = blockIdx.x, s = blockIdx.y, tid = threadIdx.x;
    size_t base = ((size_t)b * TT + s * 64) * DD;
    float s0 = 0.f, s1 = 0.f;
    #pragma unroll 4
    for (int t = 0; t < 64; ++t) {
        float v0 = x[base + (size_t)t * DD + tid];
        float v1 = x[base + (size_t)t * DD + tid + 256];
        s0 += v0; s1 += v1;
        xt[base + (size_t)t * DD + tid]       = f2tf(v0);
        xt[base + (size_t)t * DD + tid + 256] = f2tf(v1);
    }
    part[((size_t)b * 8 + s) * DD + tid]       = s0;
    part[((size_t)b * 8 + s) * DD + tid + 256] = s1;
}

__global__ void router_final(const float* __restrict__ part,
                             const float* __restrict__ Wp,
                             const float* __restrict__ bp,
                             float* __restrict__ out_tail) {
    int b = blockIdx.x, tid = threadIdx.x;
    __shared__ float pooled[DD];
    __shared__ float logits[EE];

    for (int d = tid; d < DD; d += 256) {
        float s = 0.f;
        #pragma unroll
        for (int p = 0; p < 8; ++p) s += part[((size_t)b * 8 + p) * DD + d];
        pooled[d] = s * (1.0f / TT);
    }
    __syncthreads();

    int warp = tid >> 5, lane = tid & 31;
    if (warp < EE) {
        float s = 0.f;
        for (int d = lane; d < DD; d += 32) s += pooled[d] * Wp[(size_t)d * EE + warp];
        #pragma unroll
        for (int o = 16; o > 0; o >>= 1) s += __shfl_xor_sync(0xffffffffu, s, o);
        if (lane == 0) logits[warp] = s + bp[warp];
    }
    __syncthreads();

    if (tid == 0) {
        float m = logits[0]; int arg = 0;
        #pragma unroll
        for (int e = 1; e < EE; ++e) if (logits[e] > m) { m = logits[e]; arg = e; }
        float p[EE], sum = 0.f;
        #pragma unroll
        for (int e = 0; e < EE; ++e) { p[e] = __expf(logits[e] - m); sum += p[e]; }
        float inv = 1.0f / sum;
        #pragma unroll
        for (int e = 0; e < EE; ++e) out_tail[b * EE + e] = p[e] * inv;
        out_tail[BB * EE + b] = (float)arg;
        g_expert[b] = arg;
    }
}

// ---------------- weight transpose + tf32 rounding ---------------------------
// src: [E][R][C] fp32  ->  dst: [E][C][R] tf32 bits
__global__ void transpose_tf32(const float* __restrict__ src, uint32_t* __restrict__ dst,
                               int R, int C) {
    __shared__ uint32_t tile[32][33];
    int e = blockIdx.z;
    src += (size_t)e * R * C;
    dst += (size_t)e * R * C;
    int c0 = blockIdx.x * 32, r0 = blockIdx.y * 32;
    int tx = threadIdx.x, ty = threadIdx.y;
    #pragma unroll
    for (int j = 0; j < 32; j += 8)
        tile[ty + j][tx] = f2tf(src[(size_t)(r0 + ty + j) * C + c0 + tx]);
    __syncthreads();
    #pragma unroll
    for (int j = 0; j < 32; j += 8)
        dst[(size_t)(c0 + ty + j) * R + r0 + tx] = tile[tx][ty + j];
}

// ---------------- tf32 mma.sync GEMM -----------------------------------------
// C[b](TT x ND) = act(A[b](TT x KD) @ Bt[e]^T + bias[e]);  Bt: [E][ND][KD]
// CTA tile 128x128, BK=32, 3-stage cp.async pipeline, 8 warps (warp tile 64x32).
// 2 CTAs per SM (16 warps) to hide LDSM latency and barrier bubbles.
template <int KD, int ND, bool RELU, bool OUT_TF32>
__global__ __launch_bounds__(256, 2)
void moe_gemm(const uint32_t* __restrict__ A, const uint32_t* __restrict__ Bt,
              const float* __restrict__ bias, uint32_t* __restrict__ C) {
    extern __shared__ uint8_t smraw[];
    const int tid = threadIdx.x, wid = tid >> 5, lane = tid & 31;
    const int b = blockIdx.z;
    const int e = g_expert[b];
    const int row0 = blockIdx.y * 128;
    const int col0 = blockIdx.x * 128;

    const uint32_t* Ab = A + (size_t)b * TT * KD;
    const uint32_t* Bb = Bt + (size_t)e * ND * KD;
    const float* biasb = bias + (size_t)e * ND;
    uint32_t* Cb = C + (size_t)b * TT * ND;

    const uint32_t smBase = smem_u32(smraw);
    const int lr = tid >> 3;   // loader row (0..31)
    const int lc = tid & 7;    // loader 16B chunk (0..7)

    constexpr int NC = KD / 32;

    auto issue = [&](int c) {
        if (c < NC) {
            uint32_t sA = smBase + (uint32_t)(c % 3) * 32768u;
            uint32_t sB = sA + 16384u;
            int k0 = c * 32;
            #pragma unroll
            for (int i = 0; i < 4; ++i) {
                int r = lr + 32 * i;
                cp_async16(sA + SWZ((uint32_t)(r * 128 + lc * 16)),
                           Ab + (size_t)(row0 + r) * KD + k0 + lc * 4);
            }
            #pragma unroll
            for (int i = 0; i < 4; ++i) {
                int r = lr + 32 * i;
                cp_async16(sB + SWZ((uint32_t)(r * 128 + lc * 16)),
                           Bb + (size_t)(col0 + r) * KD + k0 + lc * 4);
            }
        }
        cp_commit();
    };

    issue(0);
    issue(1);

    const int wm = wid >> 2;   // 0..1
    const int wn = wid & 3;    // 0..3
    const int mi = lane >> 3;  // ldmatrix sub-matrix index

    float acc[4][4][4];
    #pragma unroll
    for (int mt = 0; mt < 4; ++mt)
        #pragma unroll
        for (int nt = 0; nt < 4; ++nt)
            #pragma unroll
            for (int k = 0; k < 4; ++k) acc[mt][nt][k] = 0.f;

    #pragma unroll 1
    for (int c = 0; c < NC; ++c) {
        cp_wait1();
        __syncthreads();
        issue(c + 2);

        uint32_t sA = smBase + (uint32_t)(c % 3) * 32768u;
        uint32_t sB = sA + 16384u;

        #pragma unroll
        for (int ks = 0; ks < 4; ++ks) {
            uint32_t af[4][4];
            #pragma unroll
            for (int mt = 0; mt < 4; ++mt) {
                int row = wm * 64 + mt * 16 + (mi & 1) * 8 + (lane & 7);
                ldsm4(af[mt], sA + SWZ((uint32_t)(row * 128 + ks * 32 + (mi >> 1) * 16)));
            }
            uint32_t bf[2][4];
            #pragma unroll
            for (int np = 0; np < 2; ++np) {
                int row = wn * 32 + np * 16 + (mi >> 1) * 8 + (lane & 7);
                ldsm4(bf[np], sB + SWZ((uint32_t)(row * 128 + ks * 32 + (mi & 1) * 16)));
            }
            #pragma unroll
            for (int mt = 0; mt < 4; ++mt)
                #pragma unroll
                for (int nt = 0; nt < 4; ++nt) {
                    const uint32_t* bp = &bf[nt >> 1][(nt & 1) * 2];
                    mma1688(acc[mt][nt], af[mt], bp[0], bp[1]);
                }
        }
    }

    // ---------------- epilogue: bias (+relu), float2 stores ----------------
    #pragma unroll
    for (int mt = 0; mt < 4; ++mt) {
        #pragma unroll
        for (int nt = 0; nt < 4; ++nt) {
            int col = col0 + wn * 32 + nt * 8 + (lane & 3) * 2;
            float bv0 = __ldg(biasb + col);
            float bv1 = __ldg(biasb + col + 1);
            #pragma unroll
            for (int h = 0; h < 2; ++h) {
                int row = row0 + wm * 64 + mt * 16 + (lane >> 2) + h * 8;
                float v0 = acc[mt][nt][h * 2 + 0] + bv0;
                float v1 = acc[mt][nt][h * 2 + 1] + bv1;
                if (RELU) { v0 = fmaxf(v0, 0.f); v1 = fmaxf(v1, 0.f); }
                uint2 u;
                u.x = OUT_TF32 ? f2tf(v0) : __float_as_uint(v0);
                u.y = OUT_TF32 ? f2tf(v1) : __float_as_uint(v1);
                *reinterpret_cast<uint2*>(Cb + (size_t)row * ND + col) = u;
            }
        }
    }
}

// ---------------- launch -----------------------------------------------------
extern "C" void kernel_launch(void* const* d_in, const int* in_sizes, int n_in,
                              void* d_out, int out_size) {
    const float* x  = (const float*)d_in[0];
    const float* Wp = (const float*)d_in[1];
    const float* bp = (const float*)d_in[2];
    const float* W1 = (const float*)d_in[3];
    const float* b1 = (const float*)d_in[4];
    const float* W2 = (const float*)d_in[5];
    const float* b2 = (const float*)d_in[6];
    float* out = (float*)d_out;

    void *pW1t, *pW2t, *pH, *pX, *pPart;
    cudaGetSymbolAddress(&pW1t, g_W1t);
    cudaGetSymbolAddress(&pW2t, g_W2t);
    cudaGetSymbolAddress(&pH, g_h);
    cudaGetSymbolAddress(&pX, g_x);
    cudaGetSymbolAddress(&pPart, g_part);

    const int SMEM = 98304;
    cudaFuncSetAttribute(moe_gemm<DD, HH, true, true>,
                         cudaFuncAttributeMaxDynamicSharedMemorySize, SMEM);
    cudaFuncSetAttribute(moe_gemm<HH, DD, false, false>,
                         cudaFuncAttributeMaxDynamicSharedMemorySize, SMEM);
    cudaFuncSetAttribute(moe_gemm<DD, HH, true, true>,
                         cudaFuncAttributePreferredSharedMemoryCarveout, 100);
    cudaFuncSetAttribute(moe_gemm<HH, DD, false, false>,
                         cudaFuncAttributePreferredSharedMemoryCarveout, 100);

    // router + x -> tf32
    convert_pool<<<dim3(BB, 8), 256>>>(x, (uint32_t*)pX, (float*)pPart);
    router_final<<<BB, 256>>>((const float*)pPart, Wp, bp, out + (size_t)BB * TT * DD);

    // weight transposes (fp32 -> tf32 bits, K-major [E][N][K])
    transpose_tf32<<<dim3(HH / 32, DD / 32, EE), dim3(32, 8)>>>(W1, (uint32_t*)pW1t, DD, HH);
    transpose_tf32<<<dim3(DD / 32, HH / 32, EE), dim3(32, 8)>>>(W2, (uint32_t*)pW2t, HH, DD);

    // h = relu(x @ W1[e] + b1[e])
    moe_gemm<DD, HH, true, true>
        <<<dim3(HH / 128, TT / 128, BB), 256, SMEM>>>(
            (const uint32_t*)pX, (const uint32_t*)pW1t, b1, (uint32_t*)pH);

    // out = h @ W2[e] + b2[e]
    moe_gemm<HH, DD, false, false>
        <<<dim3(DD / 128, TT / 128, BB), 256, SMEM>>>(
            (const uint32_t*)pH, (const uint32_t*)pW2t, b2, (uint32_t*)out);
}

// round 5
// speedup vs baseline: 4.7080x; 1.0107x over previous
#include <cuda_runtime.h>
#include <cstdint>

#define BB 32
#define TT 512
#define DD 512
#define EE 8
#define HH 2048

// ---------------- device scratch (no cudaMalloc allowed) -------------------
__device__ uint32_t g_h[(size_t)BB * TT * HH];     // h (relu'd, tf32 bits)  128 MB
__device__ uint32_t g_x[(size_t)BB * TT * DD];     // x as tf32 bits          32 MB
__device__ uint32_t g_W1t[(size_t)EE * HH * DD];   // W1^T tf32 [E][H][D]     64 MB
__device__ uint32_t g_W2t[(size_t)EE * DD * HH];   // W2^T tf32 [E][D][H]     64 MB
__device__ float    g_part[BB * 8 * DD];
__device__ int      g_expert[BB];

// ---------------- helpers ---------------------------------------------------
__device__ __forceinline__ uint32_t smem_u32(const void* p) {
    uint32_t a;
    asm("{ .reg .u64 t; cvta.to.shared.u64 t, %1; cvt.u32.u64 %0, t; }" : "=r"(a) : "l"(p));
    return a;
}
__device__ __forceinline__ uint32_t f2tf(float x) {   // round-to-nearest tf32
    uint32_t r; asm("cvt.rn.tf32.f32 %0, %1;" : "=r"(r) : "f"(x)); return r;
}
#define SWZ(o) ((o) ^ ((((uint32_t)(o)) >> 3) & 0x70u))

__device__ __forceinline__ void cp_async16(uint32_t dst, const void* src) {
    asm volatile("cp.async.cg.shared.global [%0], [%1], 16;" :: "r"(dst), "l"(src));
}
__device__ __forceinline__ void cp_commit() {
    asm volatile("cp.async.commit_group;" ::: "memory");
}
__device__ __forceinline__ void cp_wait1() {
    asm volatile("cp.async.wait_group 1;" ::: "memory");
}
__device__ __forceinline__ void ldsm4(uint32_t* r, uint32_t addr) {
    asm volatile("ldmatrix.sync.aligned.m8n8.x4.shared.b16 {%0,%1,%2,%3}, [%4];"
                 : "=r"(r[0]), "=r"(r[1]), "=r"(r[2]), "=r"(r[3]) : "r"(addr));
}
__device__ __forceinline__ void mma1688(float* d, const uint32_t* a, uint32_t b0, uint32_t b1) {
    asm volatile("mma.sync.aligned.m16n8k8.row.col.f32.tf32.tf32.f32 "
                 "{%0,%1,%2,%3}, {%4,%5,%6,%7}, {%8,%9}, {%0,%1,%2,%3};"
                 : "+f"(d[0]), "+f"(d[1]), "+f"(d[2]), "+f"(d[3])
                 : "r"(a[0]), "r"(a[1]), "r"(a[2]), "r"(a[3]), "r"(b0), "r"(b1));
}

// ---------------- router (fused x -> tf32 convert + pooling) ----------------
__global__ void convert_pool(const float* __restrict__ x, uint32_t* __restrict__ xt,
                             float* __restrict__ part) {
    if (threadIdx.x == 0) cudaTriggerProgrammaticLaunchCompletion();
    int b = blockIdx.x, s = blockIdx.y, tid = threadIdx.x;
    size_t base = ((size_t)b * TT + s * 64) * DD;
    float s0 = 0.f, s1 = 0.f;
    #pragma unroll 4
    for (int t = 0; t < 64; ++t) {
        float v0 = x[base + (size_t)t * DD + tid];
        float v1 = x[base + (size_t)t * DD + tid + 256];
        s0 += v0; s1 += v1;
        xt[base + (size_t)t * DD + tid]       = f2tf(v0);
        xt[base + (size_t)t * DD + tid + 256] = f2tf(v1);
    }
    part[((size_t)b * 8 + s) * DD + tid]       = s0;
    part[((size_t)b * 8 + s) * DD + tid + 256] = s1;
}

__global__ void router_final(const float* __restrict__ part,
                             const float* __restrict__ Wp,
                             const float* __restrict__ bp,
                             float* __restrict__ out_tail) {
    int b = blockIdx.x, tid = threadIdx.x;
    __shared__ float pooled[DD];
    __shared__ float logits[EE];

    for (int d = tid; d < DD; d += 256) {
        float s = 0.f;
        #pragma unroll
        for (int p = 0; p < 8; ++p) s += part[((size_t)b * 8 + p) * DD + d];
        pooled[d] = s * (1.0f / TT);
    }
    __syncthreads();

    int warp = tid >> 5, lane = tid & 31;
    if (warp < EE) {
        float s = 0.f;
        for (int d = lane; d < DD; d += 32) s += pooled[d] * Wp[(size_t)d * EE + warp];
        #pragma unroll
        for (int o = 16; o > 0; o >>= 1) s += __shfl_xor_sync(0xffffffffu, s, o);
        if (lane == 0) logits[warp] = s + bp[warp];
    }
    __syncthreads();

    if (tid == 0) {
        float m = logits[0]; int arg = 0;
        #pragma unroll
        for (int e = 1; e < EE; ++e) if (logits[e] > m) { m = logits[e]; arg = e; }
        float p[EE], sum = 0.f;
        #pragma unroll
        for (int e = 0; e < EE; ++e) { p[e] = __expf(logits[e] - m); sum += p[e]; }
        float inv = 1.0f / sum;
        #pragma unroll
        for (int e = 0; e < EE; ++e) out_tail[b * EE + e] = p[e] * inv;
        out_tail[BB * EE + b] = (float)arg;
        g_expert[b] = arg;
    }
}

// ---------------- fused weight transpose + tf32 rounding ---------------------
// Handles BOTH W1 ([E][D][H] -> [E][H][D]) and W2 ([E][H][D] -> [E][D][H]).
// blockIdx.z in [0,16): z<8 -> W1 expert z; z>=8 -> W2 expert z-8.
__global__ void transpose_both(const float* __restrict__ W1, uint32_t* __restrict__ W1t,
                               const float* __restrict__ W2, uint32_t* __restrict__ W2t) {
    __shared__ uint32_t tile[32][33];
    const float* src;
    uint32_t* dst;
    int R, C, bx, by;
    int z = blockIdx.z;
    if (z < EE) {            // W1: R=D rows, C=H cols; grid (x=C/32=64, y=R/32=16)
        R = DD; C = HH;
        src = W1 + (size_t)z * R * C;
        dst = W1t + (size_t)z * R * C;
        bx = blockIdx.x; by = blockIdx.y;
    } else {                 // W2: R=H rows, C=D cols; grid mapped (x->r, y->c)
        R = HH; C = DD;
        src = W2 + (size_t)(z - EE) * R * C;
        dst = W2t + (size_t)(z - EE) * R * C;
        bx = blockIdx.y; by = blockIdx.x;   // swap: 16 c-tiles, 64 r-tiles
    }
    int c0 = bx * 32, r0 = by * 32;
    int tx = threadIdx.x, ty = threadIdx.y;
    #pragma unroll
    for (int j = 0; j < 32; j += 8)
        tile[ty + j][tx] = f2tf(src[(size_t)(r0 + ty + j) * C + c0 + tx]);
    __syncthreads();
    #pragma unroll
    for (int j = 0; j < 32; j += 8)
        dst[(size_t)(c0 + ty + j) * R + r0 + tx] = tile[tx][ty + j];
}

// ---------------- tf32 mma.sync GEMM -----------------------------------------
// C[b](TT x ND) = act(A[b](TT x KD) @ Bt[e]^T + bias[e]);  Bt: [E][ND][KD]
// CTA tile 128x128, BK=32, 3-stage cp.async pipeline, 8 warps (warp tile 64x32).
// 2 CTAs per SM. GDS: if true, kernel grid-dep-syncs at top (PDL secondary).
template <int KD, int ND, bool RELU, bool OUT_TF32, bool GDS>
__global__ __launch_bounds__(256, 2)
void moe_gemm(const uint32_t* __restrict__ A, const uint32_t* __restrict__ Bt,
              const float* __restrict__ bias, uint32_t* __restrict__ C) {
    if (GDS) {
        cudaGridDependencySynchronize();      // wait for producer grid (PDL)
    } else {
        if (threadIdx.x == 0) cudaTriggerProgrammaticLaunchCompletion();
    }
    extern __shared__ uint8_t smraw[];
    const int tid = threadIdx.x, wid = tid >> 5, lane = tid & 31;
    const int b = blockIdx.z;
    const int e = g_expert[b];
    const int row0 = blockIdx.y * 128;
    const int col0 = blockIdx.x * 128;

    const uint32_t* Ab = A + (size_t)b * TT * KD;
    const uint32_t* Bb = Bt + (size_t)e * ND * KD;
    const float* biasb = bias + (size_t)e * ND;
    uint32_t* Cb = C + (size_t)b * TT * ND;

    const uint32_t smBase = smem_u32(smraw);
    const int lr = tid >> 3;   // loader row (0..31)
    const int lc = tid & 7;    // loader 16B chunk (0..7)

    constexpr int NC = KD / 32;

    auto issue = [&](int c) {
        if (c < NC) {
            uint32_t sA = smBase + (uint32_t)(c % 3) * 32768u;
            uint32_t sB = sA + 16384u;
            int k0 = c * 32;
            #pragma unroll
            for (int i = 0; i < 4; ++i) {
                int r = lr + 32 * i;
                cp_async16(sA + SWZ((uint32_t)(r * 128 + lc * 16)),
                           Ab + (size_t)(row0 + r) * KD + k0 + lc * 4);
            }
            #pragma unroll
            for (int i = 0; i < 4; ++i) {
                int r = lr + 32 * i;
                cp_async16(sB + SWZ((uint32_t)(r * 128 + lc * 16)),
                           Bb + (size_t)(col0 + r) * KD + k0 + lc * 4);
            }
        }
        cp_commit();
    };

    issue(0);
    issue(1);

    const int wm = wid >> 2;   // 0..1
    const int wn = wid & 3;    // 0..3
    const int mi = lane >> 3;  // ldmatrix sub-matrix index

    float acc[4][4][4];
    #pragma unroll
    for (int mt = 0; mt < 4; ++mt)
        #pragma unroll
        for (int nt = 0; nt < 4; ++nt)
            #pragma unroll
            for (int k = 0; k < 4; ++k) acc[mt][nt][k] = 0.f;

    #pragma unroll 1
    for (int c = 0; c < NC; ++c) {
        cp_wait1();
        __syncthreads();
        issue(c + 2);

        uint32_t sA = smBase + (uint32_t)(c % 3) * 32768u;
        uint32_t sB = sA + 16384u;

        #pragma unroll
        for (int ks = 0; ks < 4; ++ks) {
            uint32_t af[4][4];
            #pragma unroll
            for (int mt = 0; mt < 4; ++mt) {
                int row = wm * 64 + mt * 16 + (mi & 1) * 8 + (lane & 7);
                ldsm4(af[mt], sA + SWZ((uint32_t)(row * 128 + ks * 32 + (mi >> 1) * 16)));
            }
            uint32_t bf[2][4];
            #pragma unroll
            for (int np = 0; np < 2; ++np) {
                int row = wn * 32 + np * 16 + (mi >> 1) * 8 + (lane & 7);
                ldsm4(bf[np], sB + SWZ((uint32_t)(row * 128 + ks * 32 + (mi & 1) * 16)));
            }
            #pragma unroll
            for (int mt = 0; mt < 4; ++mt)
                #pragma unroll
                for (int nt = 0; nt < 4; ++nt) {
                    const uint32_t* bp = &bf[nt >> 1][(nt & 1) * 2];
                    mma1688(acc[mt][nt], af[mt], bp[0], bp[1]);
                }
        }
    }

    // ---------------- epilogue: bias (+relu), float2 stores ----------------
    #pragma unroll
    for (int mt = 0; mt < 4; ++mt) {
        #pragma unroll
        for (int nt = 0; nt < 4; ++nt) {
            int col = col0 + wn * 32 + nt * 8 + (lane & 3) * 2;
            float bv0 = __ldg(biasb + col);
            float bv1 = __ldg(biasb + col + 1);
            #pragma unroll
            for (int h = 0; h < 2; ++h) {
                int row = row0 + wm * 64 + mt * 16 + (lane >> 2) + h * 8;
                float v0 = acc[mt][nt][h * 2 + 0] + bv0;
                float v1 = acc[mt][nt][h * 2 + 1] + bv1;
                if (RELU) { v0 = fmaxf(v0, 0.f); v1 = fmaxf(v1, 0.f); }
                uint2 u;
                u.x = OUT_TF32 ? f2tf(v0) : __float_as_uint(v0);
                u.y = OUT_TF32 ? f2tf(v1) : __float_as_uint(v1);
                *reinterpret_cast<uint2*>(Cb + (size_t)row * ND + col) = u;
            }
        }
    }
}

// ---------------- launch -----------------------------------------------------
extern "C" void kernel_launch(void* const* d_in, const int* in_sizes, int n_in,
                              void* d_out, int out_size) {
    const float* x  = (const float*)d_in[0];
    const float* Wp = (const float*)d_in[1];
    const float* bp = (const float*)d_in[2];
    const float* W1 = (const float*)d_in[3];
    const float* b1 = (const float*)d_in[4];
    const float* W2 = (const float*)d_in[5];
    const float* b2 = (const float*)d_in[6];
    float* out = (float*)d_out;

    void *pW1t, *pW2t, *pH, *pX, *pPart;
    cudaGetSymbolAddress(&pW1t, g_W1t);
    cudaGetSymbolAddress(&pW2t, g_W2t);
    cudaGetSymbolAddress(&pH, g_h);
    cudaGetSymbolAddress(&pX, g_x);
    cudaGetSymbolAddress(&pPart, g_part);

    const int SMEM = 98304;
    cudaFuncSetAttribute(moe_gemm<DD, HH, true, true, false>,
                         cudaFuncAttributeMaxDynamicSharedMemorySize, SMEM);
    cudaFuncSetAttribute(moe_gemm<HH, DD, false, false, true>,
                         cudaFuncAttributeMaxDynamicSharedMemorySize, SMEM);
    cudaFuncSetAttribute(moe_gemm<DD, HH, true, true, false>,
                         cudaFuncAttributePreferredSharedMemoryCarveout, 100);
    cudaFuncSetAttribute(moe_gemm<HH, DD, false, false, true>,
                         cudaFuncAttributePreferredSharedMemoryCarveout, 100);

    cudaLaunchAttribute pdl[1];
    pdl[0].id = cudaLaunchAttributeProgrammaticStreamSerialization;
    pdl[0].val.programmaticStreamSerializationAllowed = 1;

    // 1) convert_pool (triggers PDL at start so transposes overlap it)
    convert_pool<<<dim3(BB, 8), 256>>>(x, (uint32_t*)pX, (float*)pPart);

    // 2) weight transposes (PDL secondary: overlaps convert_pool; independent)
    {
        cudaLaunchConfig_t cfg = {};
        cfg.gridDim = dim3(64, 16, 16);
        cfg.blockDim = dim3(32, 8, 1);
        cfg.attrs = pdl; cfg.numAttrs = 1;
        cudaLaunchKernelEx(&cfg, transpose_both, W1, (uint32_t*)pW1t, W2, (uint32_t*)pW2t);
    }

    // 3) router (normal launch: waits for convert_pool AND transposes)
    router_final<<<BB, 256>>>((const float*)pPart, Wp, bp, out + (size_t)BB * TT * DD);

    // 4) GEMM1: h = relu(x @ W1[e] + b1[e])   (triggers at start for GEMM2 PDL)
    moe_gemm<DD, HH, true, true, false>
        <<<dim3(HH / 128, TT / 128, BB), 256, SMEM>>>(
            (const uint32_t*)pX, (const uint32_t*)pW1t, b1, (uint32_t*)pH);

    // 5) GEMM2: out = h @ W2[e] + b2[e]  (PDL secondary; griddepsync at top
    //    -> its CTAs fill SM slots as GEMM1's tail drains, then start instantly)
    {
        cudaLaunchConfig_t cfg = {};
        cfg.gridDim = dim3(DD / 128, TT / 128, BB);
        cfg.blockDim = dim3(256, 1, 1);
        cfg.dynamicSmemBytes = SMEM;
        cfg.attrs = pdl; cfg.numAttrs = 1;
        cudaLaunchKernelEx(&cfg, moe_gemm<HH, DD, false, false, true>,
                           (const uint32_t*)pH, (const uint32_t*)pW2t, b2, (uint32_t*)out);
    }
}

// round 6
// speedup vs baseline: 7.6486x; 1.6246x over previous
#include <cuda_runtime.h>
#include <cuda_fp16.h>
#include <cstdint>

#define BB 32
#define TT 512
#define DD 512
#define EE 8
#define HH 2048

// ---------------- device scratch (no cudaMalloc allowed) -------------------
__device__ __half g_h[(size_t)BB * TT * HH];      // h (relu'd)   64 MB
__device__ __half g_x[(size_t)BB * TT * DD];      // x as fp16    16 MB
__device__ __half g_W1t[(size_t)EE * HH * DD];    // W1^T fp16 [E][H][D] 16 MB
__device__ __half g_W2t[(size_t)EE * DD * HH];    // W2^T fp16 [E][D][H] 16 MB
__device__ float  g_part[BB * 8 * DD];
__device__ int    g_expert[BB];

// ---------------- helpers ---------------------------------------------------
__device__ __forceinline__ uint32_t smem_u32(const void* p) {
    uint32_t a;
    asm("{ .reg .u64 t; cvta.to.shared.u64 t, %1; cvt.u32.u64 %0, t; }" : "=r"(a) : "l"(p));
    return a;
}
#define SWZ(o) ((o) ^ ((((uint32_t)(o)) >> 3) & 0x70u))

__device__ __forceinline__ void cp_async16(uint32_t dst, const void* src) {
    asm volatile("cp.async.cg.shared.global [%0], [%1], 16;" :: "r"(dst), "l"(src));
}
__device__ __forceinline__ void cp_commit() {
    asm volatile("cp.async.commit_group;" ::: "memory");
}
__device__ __forceinline__ void cp_wait1() {
    asm volatile("cp.async.wait_group 1;" ::: "memory");
}
__device__ __forceinline__ void ldsm4(uint32_t* r, uint32_t addr) {
    asm volatile("ldmatrix.sync.aligned.m8n8.x4.shared.b16 {%0,%1,%2,%3}, [%4];"
                 : "=r"(r[0]), "=r"(r[1]), "=r"(r[2]), "=r"(r[3]) : "r"(addr));
}
__device__ __forceinline__ void mma16816(float* d, const uint32_t* a, uint32_t b0, uint32_t b1) {
    asm volatile("mma.sync.aligned.m16n8k16.row.col.f32.f16.f16.f32 "
                 "{%0,%1,%2,%3}, {%4,%5,%6,%7}, {%8,%9}, {%0,%1,%2,%3};"
                 : "+f"(d[0]), "+f"(d[1]), "+f"(d[2]), "+f"(d[3])
                 : "r"(a[0]), "r"(a[1]), "r"(a[2]), "r"(a[3]), "r"(b0), "r"(b1));
}

// ---------------- router (fused x -> fp16 convert + pooling) ----------------
__global__ void convert_pool(const float* __restrict__ x, __half2* __restrict__ xt,
                             float* __restrict__ part) {
    if (threadIdx.x == 0) cudaTriggerProgrammaticLaunchCompletion();
    int b = blockIdx.x, s = blockIdx.y, tid = threadIdx.x;   // tid: half2 index 0..255
    size_t base = ((size_t)b * TT + s * 64) * DD;
    float s0 = 0.f, s1 = 0.f;
    #pragma unroll 4
    for (int t = 0; t < 64; ++t) {
        float2 v = *reinterpret_cast<const float2*>(x + base + (size_t)t * DD + 2 * tid);
        s0 += v.x; s1 += v.y;
        xt[(base + (size_t)t * DD) / 2 + tid] = __floats2half2_rn(v.x, v.y);
    }
    float2 p; p.x = s0; p.y = s1;
    *reinterpret_cast<float2*>(part + ((size_t)b * 8 + s) * DD + 2 * tid) = p;
}

__global__ void router_final(const float* __restrict__ part,
                             const float* __restrict__ Wp,
                             const float* __restrict__ bp,
                             float* __restrict__ out_tail) {
    int b = blockIdx.x, tid = threadIdx.x;
    __shared__ float pooled[DD];
    __shared__ float logits[EE];

    for (int d = tid; d < DD; d += 256) {
        float s = 0.f;
        #pragma unroll
        for (int p = 0; p < 8; ++p) s += part[((size_t)b * 8 + p) * DD + d];
        pooled[d] = s * (1.0f / TT);
    }
    __syncthreads();

    int warp = tid >> 5, lane = tid & 31;
    if (warp < EE) {
        float s = 0.f;
        for (int d = lane; d < DD; d += 32) s += pooled[d] * Wp[(size_t)d * EE + warp];
        #pragma unroll
        for (int o = 16; o > 0; o >>= 1) s += __shfl_xor_sync(0xffffffffu, s, o);
        if (lane == 0) logits[warp] = s + bp[warp];
    }
    __syncthreads();

    if (tid == 0) {
        float m = logits[0]; int arg = 0;
        #pragma unroll
        for (int e = 1; e < EE; ++e) if (logits[e] > m) { m = logits[e]; arg = e; }
        float p[EE], sum = 0.f;
        #pragma unroll
        for (int e = 0; e < EE; ++e) { p[e] = __expf(logits[e] - m); sum += p[e]; }
        float inv = 1.0f / sum;
        #pragma unroll
        for (int e = 0; e < EE; ++e) out_tail[b * EE + e] = p[e] * inv;
        out_tail[BB * EE + b] = (float)arg;
        g_expert[b] = arg;
    }
}

// ---------------- fused weight transpose + fp16 rounding ---------------------
// W1 ([E][D][H] -> [E][H][D]) and W2 ([E][H][D] -> [E][D][H]) in one grid.
__global__ void transpose_both(const float* __restrict__ W1, __half* __restrict__ W1t,
                               const float* __restrict__ W2, __half* __restrict__ W2t) {
    __shared__ float tile[32][33];
    const float* src;
    __half* dst;
    int R, C, bx, by;
    int z = blockIdx.z;
    if (z < EE) {            // W1: R=D, C=H
        R = DD; C = HH;
        src = W1 + (size_t)z * R * C;
        dst = W1t + (size_t)z * R * C;
        bx = blockIdx.x; by = blockIdx.y;
    } else {                 // W2: R=H, C=D (swap grid axes)
        R = HH; C = DD;
        src = W2 + (size_t)(z - EE) * R * C;
        dst = W2t + (size_t)(z - EE) * R * C;
        bx = blockIdx.y; by = blockIdx.x;
    }
    int c0 = bx * 32, r0 = by * 32;
    int tx = threadIdx.x, ty = threadIdx.y;
    #pragma unroll
    for (int j = 0; j < 32; j += 8)
        tile[ty + j][tx] = src[(size_t)(r0 + ty + j) * C + c0 + tx];
    __syncthreads();
    #pragma unroll
    for (int j = 0; j < 32; j += 8)
        dst[(size_t)(c0 + ty + j) * R + r0 + tx] = __float2half_rn(tile[tx][ty + j]);
}

// ---------------- fp16 mma.sync GEMM -----------------------------------------
// C[b](TT x ND) = act(A[b](TT x KD) @ Bt[e]^T + bias[e]);  Bt: [E][ND][KD] fp16
// CTA tile 128x128, BK=64 halves (128B rows), 3-stage cp.async, 8 warps 64x32.
// 2 CTAs/SM. GDS: PDL secondary grid-dep-sync.
template <int KD, int ND, bool RELU, bool OUT_HALF, bool GDS>
__global__ __launch_bounds__(256, 2)
void moe_gemm(const __half* __restrict__ A, const __half* __restrict__ Bt,
              const float* __restrict__ bias, void* __restrict__ Cv) {
    if (GDS) {
        cudaGridDependencySynchronize();
    } else {
        if (threadIdx.x == 0) cudaTriggerProgrammaticLaunchCompletion();
    }
    extern __shared__ uint8_t smraw[];
    const int tid = threadIdx.x, wid = tid >> 5, lane = tid & 31;
    const int b = blockIdx.z;
    const int e = g_expert[b];
    const int row0 = blockIdx.y * 128;
    const int col0 = blockIdx.x * 128;

    const __half* Ab = A + (size_t)b * TT * KD;
    const __half* Bb = Bt + (size_t)e * ND * KD;
    const float* biasb = bias + (size_t)e * ND;

    const uint32_t smBase = smem_u32(smraw);
    const int lr = tid >> 3;   // loader row (0..31)
    const int lc = tid & 7;    // loader 16B chunk (0..7) -> 8 halves

    constexpr int NC = KD / 64;

    auto issue = [&](int c) {
        if (c < NC) {
            uint32_t sA = smBase + (uint32_t)(c % 3) * 32768u;
            uint32_t sB = sA + 16384u;
            int k0 = c * 64;
            #pragma unroll
            for (int i = 0; i < 4; ++i) {
                int r = lr + 32 * i;
                cp_async16(sA + SWZ((uint32_t)(r * 128 + lc * 16)),
                           Ab + (size_t)(row0 + r) * KD + k0 + lc * 8);
            }
            #pragma unroll
            for (int i = 0; i < 4; ++i) {
                int r = lr + 32 * i;
                cp_async16(sB + SWZ((uint32_t)(r * 128 + lc * 16)),
                           Bb + (size_t)(col0 + r) * KD + k0 + lc * 8);
            }
        }
        cp_commit();
    };

    issue(0);
    issue(1);

    const int wm = wid >> 2;   // 0..1
    const int wn = wid & 3;    // 0..3

    // ldmatrix lane addressing
    const int aRow = lane & 15;          // A: row within 16-row tile
    const int aColB = (lane >> 4) * 16;  // A: 16B col half (k 0-7 / 8-15)
    const int bRow = ((lane >> 4) & 1) * 8 + (lane & 7);  // B: n row within 16
    const int bColB = ((lane >> 3) & 1) * 16;             // B: k-half bytes

    float acc[4][4][4];
    #pragma unroll
    for (int mt = 0; mt < 4; ++mt)
        #pragma unroll
        for (int nt = 0; nt < 4; ++nt)
            #pragma unroll
            for (int k = 0; k < 4; ++k) acc[mt][nt][k] = 0.f;

    #pragma unroll 1
    for (int c = 0; c < NC; ++c) {
        cp_wait1();
        __syncthreads();
        issue(c + 2);

        uint32_t sA = smBase + (uint32_t)(c % 3) * 32768u;
        uint32_t sB = sA + 16384u;

        #pragma unroll
        for (int ks = 0; ks < 4; ++ks) {        // 4 x k16 per 64-half chunk
            uint32_t af[4][4];
            #pragma unroll
            for (int mt = 0; mt < 4; ++mt) {
                int row = wm * 64 + mt * 16 + aRow;
                ldsm4(af[mt], sA + SWZ((uint32_t)(row * 128 + ks * 32 + aColB)));
            }
            uint32_t bf[2][4];
            #pragma unroll
            for (int np = 0; np < 2; ++np) {
                int row = wn * 32 + np * 16 + bRow;
                ldsm4(bf[np], sB + SWZ((uint32_t)(row * 128 + ks * 32 + bColB)));
            }
            #pragma unroll
            for (int mt = 0; mt < 4; ++mt)
                #pragma unroll
                for (int nt = 0; nt < 4; ++nt) {
                    const uint32_t* bp = &bf[nt >> 1][(nt & 1) * 2];
                    mma16816(acc[mt][nt], af[mt], bp[0], bp[1]);
                }
        }
    }

    // ---------------- epilogue: bias (+relu) ----------------
    #pragma unroll
    for (int mt = 0; mt < 4; ++mt) {
        #pragma unroll
        for (int nt = 0; nt < 4; ++nt) {
            int col = col0 + wn * 32 + nt * 8 + (lane & 3) * 2;
            float bv0 = __ldg(biasb + col);
            float bv1 = __ldg(biasb + col + 1);
            #pragma unroll
            for (int h = 0; h < 2; ++h) {
                int row = row0 + wm * 64 + mt * 16 + (lane >> 2) + h * 8;
                float v0 = acc[mt][nt][h * 2 + 0] + bv0;
                float v1 = acc[mt][nt][h * 2 + 1] + bv1;
                if (RELU) { v0 = fmaxf(v0, 0.f); v1 = fmaxf(v1, 0.f); }
                if (OUT_HALF) {
                    __half2* Ch = (__half2*)((__half*)Cv + (size_t)b * TT * ND);
                    Ch[((size_t)row * ND + col) / 2] = __floats2half2_rn(v0, v1);
                } else {
                    float2 u; u.x = v0; u.y = v1;
                    *reinterpret_cast<float2*>((float*)Cv + (size_t)b * TT * ND +
                                               (size_t)row * ND + col) = u;
                }
            }
        }
    }
}

// ---------------- launch -----------------------------------------------------
extern "C" void kernel_launch(void* const* d_in, const int* in_sizes, int n_in,
                              void* d_out, int out_size) {
    const float* x  = (const float*)d_in[0];
    const float* Wp = (const float*)d_in[1];
    const float* bp = (const float*)d_in[2];
    const float* W1 = (const float*)d_in[3];
    const float* b1 = (const float*)d_in[4];
    const float* W2 = (const float*)d_in[5];
    const float* b2 = (const float*)d_in[6];
    float* out = (float*)d_out;

    void *pW1t, *pW2t, *pH, *pX, *pPart;
    cudaGetSymbolAddress(&pW1t, g_W1t);
    cudaGetSymbolAddress(&pW2t, g_W2t);
    cudaGetSymbolAddress(&pH, g_h);
    cudaGetSymbolAddress(&pX, g_x);
    cudaGetSymbolAddress(&pPart, g_part);

    const int SMEM = 98304;
    cudaFuncSetAttribute(moe_gemm<DD, HH, true, true, false>,
                         cudaFuncAttributeMaxDynamicSharedMemorySize, SMEM);
    cudaFuncSetAttribute(moe_gemm<HH, DD, false, false, true>,
                         cudaFuncAttributeMaxDynamicSharedMemorySize, SMEM);
    cudaFuncSetAttribute(moe_gemm<DD, HH, true, true, false>,
                         cudaFuncAttributePreferredSharedMemoryCarveout, 100);
    cudaFuncSetAttribute(moe_gemm<HH, DD, false, false, true>,
                         cudaFuncAttributePreferredSharedMemoryCarveout, 100);

    cudaLaunchAttribute pdl[1];
    pdl[0].id = cudaLaunchAttributeProgrammaticStreamSerialization;
    pdl[0].val.programmaticStreamSerializationAllowed = 1;

    // 1) convert_pool (triggers PDL at start so transposes overlap it)
    convert_pool<<<dim3(BB, 8), 256>>>(x, (__half2*)pX, (float*)pPart);

    // 2) weight transposes (PDL secondary: overlaps convert_pool)
    {
        cudaLaunchConfig_t cfg = {};
        cfg.gridDim = dim3(64, 16, 16);
        cfg.blockDim = dim3(32, 8, 1);
        cfg.attrs = pdl; cfg.numAttrs = 1;
        cudaLaunchKernelEx(&cfg, transpose_both, W1, (__half*)pW1t, W2, (__half*)pW2t);
    }

    // 3) router (normal launch: waits for all priors)
    router_final<<<BB, 256>>>((const float*)pPart, Wp, bp, out + (size_t)BB * TT * DD);

    // 4) GEMM1: h = relu(x @ W1[e] + b1[e]), fp16 out
    moe_gemm<DD, HH, true, true, false>
        <<<dim3(HH / 128, TT / 128, BB), 256, SMEM>>>(
            (const __half*)pX, (const __half*)pW1t, b1, pH);

    // 5) GEMM2: out = h @ W2[e] + b2[e], fp32 out (PDL secondary)
    {
        cudaLaunchConfig_t cfg = {};
        cfg.gridDim = dim3(DD / 128, TT / 128, BB);
        cfg.blockDim = dim3(256, 1, 1);
        cfg.dynamicSmemBytes = SMEM;
        cfg.attrs = pdl; cfg.numAttrs = 1;
        cudaLaunchKernelEx(&cfg, moe_gemm<HH, DD, false, false, true>,
                           (const __half*)pH, (const __half*)pW2t, b2, (void*)out);
    }
}